// round 5
// baseline (speedup 1.0000x reference)
#include <cuda_runtime.h>
#include <math.h>

#define NRBF 32
#define RCAP 131072
__device__ float4 g_R4[RCAP];

// step = 5/31, width = 5/32
#define STEP      (0.16129032258064516f)
#define INV_W     (6.4f)
#define S_RATIO   (1.03225806451612903f)   // step/width
#define HALF_S2   (0.53277835587929240f)   // 0.5*(step/width)^2
#define G_CONST   (0.34453600290f)         // exp(-(step/width)^2)
#define R_CUTF    (5.0f)
#define U0_MAX    (12.0f)                  // beyond |u0|=12 the whole quad < 1e-17

#define C1  (0.48860251190291992f)
#define C2A (1.09254843059207907f)
#define C2B (0.31539156525252005f)
#define C2C (0.54627421529603953f)

// FMA/ALU-only expf (no MUFU). Caller guarantees x in [-75, +13].
__device__ __forceinline__ float fast_exp(float x) {
    float t  = x * 1.44269504f;
    float fi = rintf(t);
    int   ei = (int)fi;
    float g  = fmaf(fi, -0.693147182f, x);
    float p  = 1.9875691500e-4f;
    p = fmaf(p, g, 1.3981999507e-3f);
    p = fmaf(p, g, 8.3334519073e-3f);
    p = fmaf(p, g, 4.1665795894e-2f);
    p = fmaf(p, g, 1.6666665459e-1f);
    p = fmaf(p, g, 5.0000001201e-1f);
    float e = fmaf(g * g, p, g) + 1.0f;
    return __int_as_float(__float_as_int(e) + (ei << 23));
}

__global__ void __launch_bounds__(256)
pack_R_kernel(const float* __restrict__ R, int n)
{
    int i = blockIdx.x * 256 + threadIdx.x;
    if (i < n) {
        g_R4[i] = make_float4(R[3*(size_t)i], R[3*(size_t)i + 1],
                              R[3*(size_t)i + 2], 0.f);
    }
}

// 8 threads per pair: thread (p, c) computes rbf[4c..4c+3] and channel c of sph.
__global__ void __launch_bounds__(256)
geo_kernel(const float* __restrict__ pair_mask,
           const float* __restrict__ point_mask,
           const int*   __restrict__ idx_i,
           const int*   __restrict__ idx_j,
           float4* __restrict__ rbf_out4,
           float*  __restrict__ chi_out,
           int n_pairs)
{
    const int tid  = threadIdx.x;
    const int lane = tid & 31;
    const int c    = lane & 7;      // chunk / channel
    const int slot = lane >> 3;     // pair slot within warp (0..3)
    const long long g = (long long)blockIdx.x * 256 + tid;
    const long long p = g >> 3;
    const bool valid  = (p < (long long)n_pairs);

    int i = 0, j = 0;
    float pm = 0.f;
    if (valid) {
        i  = __ldg(idx_i + p);      // replicated x8 -> single sector per warp
        j  = __ldg(idx_j + p);
        pm = __ldg(pair_mask + p);
    }

    float rx = 0.f, ry = 0.f, rz = 0.f;
    if (valid) {
        const float4 a = g_R4[j];
        const float4 b = g_R4[i];
        rx = (a.x - b.x) * pm;
        ry = (a.y - b.y) * pm;
        rz = (a.z - b.z) * pm;
    }

    const float sq  = fmaf(rx, rx, fmaf(ry, ry, rz * rz));
    const float inv = (sq > 0.f) ? rsqrtf(sq) : 0.f;
    const float d   = sq * inv * pm;

    // ---- rbf quad k = 4c .. 4c+3: two-side-guarded anchor + 3 ratio steps ----
    const float u0   = (d - (float)(4 * c) * STEP) * INV_W;
    const float u0r  = fminf(fmaxf(u0, -U0_MAX), U0_MAX);     // exp args in range
    const float kill = (fabsf(u0) < U0_MAX) ? pm : 0.f;       // far quads -> exact 0
    const float x0 = fast_exp(-0.5f * u0r * u0r) * kill;      // 0 propagates down
    float q        = fast_exp(fmaf(u0r, S_RATIO, -HALF_S2));  // bounded <= 1.4e5
    const float x1 = x0 * q;  q *= G_CONST;
    const float x2 = x1 * q;  q *= G_CONST;
    const float x3 = x2 * q;
    if (valid) {
        __stcs(rbf_out4 + g, make_float4(x0, x1, x2, x3));
    }

    // ---- phi (cutoff): cos(pi*x) = -sin(pi*(x-1/2)) odd polynomial ----
    const float xx = d * 0.2f;
    const float h  = xx - 0.5f;
    const float v  = h * h;
    float sp = fmaf(v, fmaf(v, fmaf(v, fmaf(v, 0.0821458866f, -0.599264529f),
                                    2.55016404f), -5.16771278f), 3.14159265f);
    const float cospix = -h * sp;
    const float phi = (d < R_CUTF) ? 0.5f * (cospix + 1.0f) * pm : 0.f;

    // ---- spherical harmonics: this lane handles channel c only ----
    const float um = (d != 0.f) ? inv : 0.f;
    const float ux = rx * um * pm;
    const float uy = ry * um * pm;
    const float uz = rz * um * pm;

    const float pmi   = valid ? __ldg(point_mask + i) : 0.f;
    const float scale = phi * pm * pmi;

    const float v0 = C1 * uy;
    const float v1 = C1 * uz;
    const float v2 = C1 * ux;
    const float v3 = C2A * ux * uy;
    const float v4 = C2A * uy * uz;
    const float v5 = C2B * fmaf(3.f, uz * uz, -1.f);
    const float v6 = C2A * ux * uz;
    const float v7 = C2C * (ux * ux - uy * uy);

    const bool b0 = c & 1, b1 = c & 2, b2 = c & 4;
    const float t0_ = b0 ? v1 : v0;
    const float t1_ = b0 ? v3 : v2;
    const float t2_ = b0 ? v5 : v4;
    const float t3_ = b0 ? v7 : v6;
    const float s0  = b1 ? t1_ : t0_;
    const float s1  = b1 ? t3_ : t2_;
    float val = (b2 ? s1 : s0) * scale;

    // ---- segmented reduction across the 4 pair-slots (idx_i sorted) ----
    int ii = valid ? i : -1;
    const unsigned full = 0xffffffffu;
    {
        int   i8 = __shfl_down_sync(full, ii, 8);
        float f8 = __shfl_down_sync(full, val, 8);
        if (slot < 3 && i8 == ii) val += f8;
        int   i16 = __shfl_down_sync(full, ii, 16);
        float f16 = __shfl_down_sync(full, val, 16);
        if (slot < 2 && i16 == ii) val += f16;
    }
    int iprev = __shfl_up_sync(full, ii, 8);
    bool leader = (slot == 0) || (iprev != ii);
    if (leader && valid) {
        atomicAdd(chi_out + (size_t)ii * 8 + c, val);
    }
}

extern "C" void kernel_launch(void* const* d_in, const int* in_sizes, int n_in,
                              void* d_out, int out_size)
{
    const float* R          = (const float*)d_in[0];
    const float* pair_mask  = (const float*)d_in[1];
    const float* point_mask = (const float*)d_in[2];
    const int*   idx_i      = (const int*)d_in[3];
    const int*   idx_j      = (const int*)d_in[4];

    const int n_pairs = in_sizes[1];
    const int n       = in_sizes[2];

    float* rbf_out = (float*)d_out;
    float* chi_out = rbf_out + (size_t)n_pairs * NRBF;

    cudaMemsetAsync(chi_out, 0, (size_t)n * 8 * sizeof(float), 0);

    pack_R_kernel<<<(n + 255) / 256, 256>>>(R, n);

    long long total = (long long)n_pairs * 8;
    int blocks = (int)((total + 255) / 256);
    geo_kernel<<<blocks, 256>>>(pair_mask, point_mask, idx_i, idx_j,
                                (float4*)rbf_out, chi_out, n_pairs);
}

// round 6
// speedup vs baseline: 1.3525x; 1.3525x over previous
#include <cuda_runtime.h>
#include <math.h>

#define NRBF 32
#define RCAP 131072
__device__ float4 g_R4[RCAP];

// step = 5/31, width = 5/32
#define STEP      (0.16129032258064516f)
#define INV_W     (6.4f)
#define S_RATIO   (1.03225806451612903f)   // step/width
#define HALF_S2   (0.53277835587929240f)   // 0.5*(step/width)^2
#define G_CONST   (0.34453600290f)         // exp(-(step/width)^2)
#define R_CUTF    (5.0f)
#define U0_MAX    (13.0f)   // |u0|>13 -> largest true value in chunk < 1.4e-5

#define C1  (0.48860251190291992f)
#define C2A (1.09254843059207907f)
#define C2B (0.31539156525252005f)
#define C2C (0.54627421529603953f)

// FMA/ALU-only expf (no MUFU). Valid for x in [-85, +14].
__device__ __forceinline__ float fast_exp(float x) {
    float t  = x * 1.44269504f;
    float fi = rintf(t);
    int   ei = (int)fi;
    float g  = fmaf(fi, -0.693147182f, x);
    float p  = 1.9875691500e-4f;
    p = fmaf(p, g, 1.3981999507e-3f);
    p = fmaf(p, g, 8.3334519073e-3f);
    p = fmaf(p, g, 4.1665795894e-2f);
    p = fmaf(p, g, 1.6666665459e-1f);
    p = fmaf(p, g, 5.0000001201e-1f);
    float e = fmaf(g * g, p, g) + 1.0f;
    return __int_as_float(__float_as_int(e) + (ei << 23));
}

__global__ void __launch_bounds__(256)
pack_R_kernel(const float* __restrict__ R, int n)
{
    int i = blockIdx.x * 256 + threadIdx.x;
    if (i < n) {
        g_R4[i] = make_float4(R[3*(size_t)i], R[3*(size_t)i + 1],
                              R[3*(size_t)i + 2], 0.f);
    }
}

// 2 threads per pair: thread (p, h) computes rbf[16h .. 16h+15] (register-
// resident, mid-chunk anchor + two-sided ladder) and sph channels [4h, 4h+4).
__global__ void __launch_bounds__(256)
geo_kernel(const float* __restrict__ pair_mask,
           const float* __restrict__ point_mask,
           const int*   __restrict__ idx_i,
           const int*   __restrict__ idx_j,
           float4* __restrict__ rbf_out4,
           float*  __restrict__ chi_out,
           int n_pairs)
{
    const int tid  = threadIdx.x;
    const int lane = tid & 31;
    const int h    = lane & 1;          // half-row / channel group
    const long long gt = (long long)blockIdx.x * 256 + tid;
    const long long p  = gt >> 1;
    const bool valid   = (p < (long long)n_pairs);

    int i = 0, j = 0;
    float pm = 0.f;
    if (valid) {
        i  = __ldg(idx_i + p);          // x2 dup -> coalesced
        j  = __ldg(idx_j + p);
        pm = __ldg(pair_mask + p);
    }

    float rx = 0.f, ry = 0.f, rz = 0.f;
    if (valid) {
        const float4 a = g_R4[j];
        const float4 b = g_R4[i];
        rx = (a.x - b.x) * pm;
        ry = (a.y - b.y) * pm;
        rz = (a.z - b.z) * pm;
    }

    const float sq  = fmaf(rx, rx, fmaf(ry, ry, rz * rz));
    const float inv = (sq > 0.f) ? rsqrtf(sq) : 0.f;
    const float d   = sq * inv * pm;

    // ---- rbf half-row: anchor at k = 16h+8 (mid-chunk), two-sided ladder ----
    const float cm   = (float)(16 * h + 8) * STEP;
    const float u0   = (d - cm) * INV_W;
    const float u0r  = fminf(fmaxf(u0, -U0_MAX), U0_MAX);
    const float kill = (fabsf(u0) < U0_MAX) ? pm : 0.f;
    const float A  = fast_exp(-0.5f * u0r * u0r) * kill;          // anchor (rel 8)
    const float qu = fast_exp(fmaf(u0r, S_RATIO, -HALF_S2));      // up ratio
    float rq = __uint_as_float(0x7EF311C3u - __float_as_uint(qu)); // qd = G/qu
    rq = rq * (2.0f - qu * rq);
    rq = rq * (2.0f - qu * rq);
    rq = rq * (2.0f - qu * rq);
    const float qd = G_CONST * rq;                                 // down ratio

    float x[16];
    x[8] = A;
    {   // down: rel 7..0
        float r = A, q = qd;
        #pragma unroll
        for (int m = 7; m >= 0; --m) { r *= q; q *= G_CONST; x[m] = r; }
    }
    {   // up: rel 9..15
        float r = A, q = qu;
        #pragma unroll
        for (int m = 9; m < 16; ++m) { r *= q; q *= G_CONST; x[m] = r; }
    }
    if (valid) {
        float4* o = rbf_out4 + p * 8 + h * 4;
        __stcs(o + 0, make_float4(x[0],  x[1],  x[2],  x[3]));
        __stcs(o + 1, make_float4(x[4],  x[5],  x[6],  x[7]));
        __stcs(o + 2, make_float4(x[8],  x[9],  x[10], x[11]));
        __stcs(o + 3, make_float4(x[12], x[13], x[14], x[15]));
    }

    // ---- phi (cutoff): cos(pi*x) = -sin(pi*(x-1/2)) odd polynomial ----
    const float xx = d * 0.2f;
    const float hh = xx - 0.5f;
    const float v  = hh * hh;
    float sp = fmaf(v, fmaf(v, fmaf(v, fmaf(v, 0.0821458866f, -0.599264529f),
                                    2.55016404f), -5.16771278f), 3.14159265f);
    const float cospix = -hh * sp;
    const float phi = (d < R_CUTF) ? 0.5f * (cospix + 1.0f) * pm : 0.f;

    // ---- spherical harmonics: this thread owns channels [4h, 4h+4) ----
    const float um = (d != 0.f) ? inv : 0.f;
    const float ux = rx * um * pm;
    const float uy = ry * um * pm;
    const float uz = rz * um * pm;

    const float pmi   = valid ? __ldg(point_mask + i) : 0.f;
    const float scale = phi * pm * pmi;

    const float lo0 = C1 * uy;
    const float lo1 = C1 * uz;
    const float lo2 = C1 * ux;
    const float lo3 = C2A * ux * uy;
    const float hi0 = C2A * uy * uz;
    const float hi1 = C2B * fmaf(3.f, uz * uz, -1.f);
    const float hi2 = C2A * ux * uz;
    const float hi3 = C2C * (ux * ux - uy * uy);

    float val0 = (h ? hi0 : lo0) * scale;
    float val1 = (h ? hi1 : lo1) * scale;
    float val2 = (h ? hi2 : lo2) * scale;
    float val3 = (h ? hi3 : lo3) * scale;

    // ---- segmented reduction over the 16 pair-slots (even offsets keep h) ----
    int ii = valid ? i : -1;
    const unsigned full = 0xffffffffu;
    #pragma unroll
    for (int off = 2; off < 32; off <<= 1) {
        int   i2 = __shfl_down_sync(full, ii, off);
        bool take = (lane + off < 32) && (i2 == ii);
        float f0 = __shfl_down_sync(full, val0, off);
        float f1 = __shfl_down_sync(full, val1, off);
        float f2 = __shfl_down_sync(full, val2, off);
        float f3 = __shfl_down_sync(full, val3, off);
        if (take) { val0 += f0; val1 += f1; val2 += f2; val3 += f3; }
    }
    int iprev = __shfl_up_sync(full, ii, 2);
    bool leader = (lane < 2) || (iprev != ii);
    if (leader && valid) {
        float* dst = chi_out + (size_t)ii * 8 + 4 * h;
        atomicAdd(dst + 0, val0);
        atomicAdd(dst + 1, val1);
        atomicAdd(dst + 2, val2);
        atomicAdd(dst + 3, val3);
    }
}

extern "C" void kernel_launch(void* const* d_in, const int* in_sizes, int n_in,
                              void* d_out, int out_size)
{
    const float* R          = (const float*)d_in[0];
    const float* pair_mask  = (const float*)d_in[1];
    const float* point_mask = (const float*)d_in[2];
    const int*   idx_i      = (const int*)d_in[3];
    const int*   idx_j      = (const int*)d_in[4];

    const int n_pairs = in_sizes[1];
    const int n       = in_sizes[2];

    float* rbf_out = (float*)d_out;
    float* chi_out = rbf_out + (size_t)n_pairs * NRBF;

    cudaMemsetAsync(chi_out, 0, (size_t)n * 8 * sizeof(float), 0);

    pack_R_kernel<<<(n + 255) / 256, 256>>>(R, n);

    long long total = (long long)n_pairs * 2;
    int blocks = (int)((total + 255) / 256);
    geo_kernel<<<blocks, 256>>>(pair_mask, point_mask, idx_i, idx_j,
                                (float4*)rbf_out, chi_out, n_pairs);
}

// round 7
// speedup vs baseline: 1.5964x; 1.1803x over previous
#include <cuda_runtime.h>
#include <math.h>
#include <stdint.h>

#define NRBF 32
#define RCAP 131072
__device__ float4 g_R4[RCAP];

// step = 5/31, width = 5/32
#define STEP      (0.16129032258064516f)
#define INV_W     (6.4f)
#define S_RATIO   (1.03225806451612903f)   // step/width
#define HALF_S2   (0.53277835587929240f)   // 0.5*(step/width)^2
#define G_CONST   (0.34453600290f)         // exp(-(step/width)^2)
#define R_CUTF    (5.0f)
#define U0_MAX    (13.0f)

#define C1  (0.48860251190291992f)
#define C2A (1.09254843059207907f)
#define C2B (0.31539156525252005f)
#define C2C (0.54627421529603953f)

#define PAIRS_PER_BLOCK 128   // 256 threads, 2 per pair
#define TILE_BYTES (PAIRS_PER_BLOCK * NRBF * 4)   // 16 KB

// FMA/ALU-only expf (no MUFU). Valid for x in [-85, +14].
__device__ __forceinline__ float fast_exp(float x) {
    float t  = x * 1.44269504f;
    float fi = rintf(t);
    int   ei = (int)fi;
    float g  = fmaf(fi, -0.693147182f, x);
    float p  = 1.9875691500e-4f;
    p = fmaf(p, g, 1.3981999507e-3f);
    p = fmaf(p, g, 8.3334519073e-3f);
    p = fmaf(p, g, 4.1665795894e-2f);
    p = fmaf(p, g, 1.6666665459e-1f);
    p = fmaf(p, g, 5.0000001201e-1f);
    float e = fmaf(g * g, p, g) + 1.0f;
    return __int_as_float(__float_as_int(e) + (ei << 23));
}

__global__ void __launch_bounds__(256)
pack_R_kernel(const float* __restrict__ R, int n)
{
    int i = blockIdx.x * 256 + threadIdx.x;
    if (i < n) {
        g_R4[i] = make_float4(R[3*(size_t)i], R[3*(size_t)i + 1],
                              R[3*(size_t)i + 2], 0.f);
    }
}

// 2 threads per pair: thread (p, h) computes rbf[16h..16h+15] (register ladder)
// and sph channels [4h, 4h+4). rbf goes out via smem tile + cp.async.bulk.
__global__ void __launch_bounds__(256)
geo_kernel(const float* __restrict__ pair_mask,
           const float* __restrict__ point_mask,
           const int*   __restrict__ idx_i,
           const int*   __restrict__ idx_j,
           float* __restrict__ rbf_out,
           float* __restrict__ chi_out,
           int n_pairs)
{
    __shared__ __align__(16) float tile[PAIRS_PER_BLOCK * NRBF];

    const int tid  = threadIdx.x;
    const int lane = tid & 31;
    const int s    = tid >> 1;          // pair index within block (0..127)
    const int h    = tid & 1;           // half-row / channel group
    const long long p = (long long)blockIdx.x * PAIRS_PER_BLOCK + s;
    const bool valid  = (p < (long long)n_pairs);

    int i = 0, j = 0;
    float pm = 0.f;
    if (valid) {
        i  = __ldg(idx_i + p);
        j  = __ldg(idx_j + p);
        pm = __ldg(pair_mask + p);
    }

    float rx = 0.f, ry = 0.f, rz = 0.f;
    if (valid) {
        const float4 a = g_R4[j];
        const float4 b = g_R4[i];
        rx = (a.x - b.x) * pm;
        ry = (a.y - b.y) * pm;
        rz = (a.z - b.z) * pm;
    }

    const float sq  = fmaf(rx, rx, fmaf(ry, ry, rz * rz));
    const float inv = (sq > 0.f) ? rsqrtf(sq) : 0.f;
    const float d   = sq * inv * pm;

    // ---- rbf half-row: anchor at k = 16h+8, two-sided ladder ----
    const float cm   = (float)(16 * h + 8) * STEP;
    const float u0   = (d - cm) * INV_W;
    const float u0r  = fminf(fmaxf(u0, -U0_MAX), U0_MAX);
    const float kill = (fabsf(u0) < U0_MAX) ? pm : 0.f;
    const float A  = fast_exp(-0.5f * u0r * u0r) * kill;
    const float qu = fast_exp(fmaf(u0r, S_RATIO, -HALF_S2));
    float rq = __uint_as_float(0x7EF311C3u - __float_as_uint(qu));
    rq = rq * (2.0f - qu * rq);
    rq = rq * (2.0f - qu * rq);
    rq = rq * (2.0f - qu * rq);
    const float qd = G_CONST * rq;

    float x[16];
    x[8] = A;
    {
        float r = A, q = qd;
        #pragma unroll
        for (int m = 7; m >= 0; --m) { r *= q; q *= G_CONST; x[m] = r; }
    }
    {
        float r = A, q = qu;
        #pragma unroll
        for (int m = 9; m < 16; ++m) { r *= q; q *= G_CONST; x[m] = r; }
    }

    // ---- conflict-free STS: at slot t, store quad (t+s)&3 at its true addr ----
    {
        const float4 Q0 = make_float4(x[0],  x[1],  x[2],  x[3]);
        const float4 Q1 = make_float4(x[4],  x[5],  x[6],  x[7]);
        const float4 Q2 = make_float4(x[8],  x[9],  x[10], x[11]);
        const float4 Q3 = make_float4(x[12], x[13], x[14], x[15]);
        char* rowp = (char*)tile + s * 128 + h * 64;
        #pragma unroll
        for (int t = 0; t < 4; ++t) {
            int q = (t + s) & 3;
            float4 a0 = (q & 1) ? Q1 : Q0;
            float4 a1 = (q & 1) ? Q3 : Q2;
            float4 r  = (q & 2) ? a1 : a0;
            *(float4*)(rowp + q * 16) = r;
        }
    }

    // ---- phi (cutoff): cos(pi*x) = -sin(pi*(x-1/2)) odd polynomial ----
    const float xx = d * 0.2f;
    const float hh = xx - 0.5f;
    const float v  = hh * hh;
    float sp = fmaf(v, fmaf(v, fmaf(v, fmaf(v, 0.0821458866f, -0.599264529f),
                                    2.55016404f), -5.16771278f), 3.14159265f);
    const float cospix = -hh * sp;
    const float phi = (d < R_CUTF) ? 0.5f * (cospix + 1.0f) * pm : 0.f;

    // ---- spherical harmonics: channels [4h, 4h+4) ----
    const float um = (d != 0.f) ? inv : 0.f;
    const float ux = rx * um * pm;
    const float uy = ry * um * pm;
    const float uz = rz * um * pm;

    const float pmi   = valid ? __ldg(point_mask + i) : 0.f;
    const float scale = phi * pm * pmi;

    const float lo0 = C1 * uy;
    const float lo1 = C1 * uz;
    const float lo2 = C1 * ux;
    const float lo3 = C2A * ux * uy;
    const float hi0 = C2A * uy * uz;
    const float hi1 = C2B * fmaf(3.f, uz * uz, -1.f);
    const float hi2 = C2A * ux * uz;
    const float hi3 = C2C * (ux * ux - uy * uy);

    float val0 = (h ? hi0 : lo0) * scale;
    float val1 = (h ? hi1 : lo1) * scale;
    float val2 = (h ? hi2 : lo2) * scale;
    float val3 = (h ? hi3 : lo3) * scale;

    // ---- segmented reduction over the 16 pair-slots (even offsets keep h) ----
    int ii = valid ? i : -1;
    const unsigned full = 0xffffffffu;
    #pragma unroll
    for (int off = 2; off < 32; off <<= 1) {
        int   i2 = __shfl_down_sync(full, ii, off);
        bool take = (lane + off < 32) && (i2 == ii);
        float f0 = __shfl_down_sync(full, val0, off);
        float f1 = __shfl_down_sync(full, val1, off);
        float f2 = __shfl_down_sync(full, val2, off);
        float f3 = __shfl_down_sync(full, val3, off);
        if (take) { val0 += f0; val1 += f1; val2 += f2; val3 += f3; }
    }
    int iprev = __shfl_up_sync(full, ii, 2);
    bool leader = (lane < 2) || (iprev != ii);
    if (leader && valid) {
        float* dst = chi_out + (size_t)ii * 8 + 4 * h;
        atomicAdd(dst + 0, val0);
        atomicAdd(dst + 1, val1);
        atomicAdd(dst + 2, val2);
        atomicAdd(dst + 3, val3);
    }

    // ---- bulk copy tile -> global (UBLKCP path, off the L1 warp path) ----
    __syncthreads();
    if (tid == 0) {
        asm volatile("fence.proxy.async.shared::cta;" ::: "memory");
        long long p0   = (long long)blockIdx.x * PAIRS_PER_BLOCK;
        long long rows = (long long)n_pairs - p0;
        int nrows = (rows >= PAIRS_PER_BLOCK) ? PAIRS_PER_BLOCK : (int)rows;
        unsigned bytes = (unsigned)nrows * (NRBF * 4);
        uint32_t saddr;
        asm("{ .reg .u64 t; cvta.to.shared.u64 t, %1; cvt.u32.u64 %0, t; }"
            : "=r"(saddr) : "l"(tile));
        unsigned long long gaddr =
            (unsigned long long)(rbf_out + (size_t)p0 * NRBF);
        asm volatile("cp.async.bulk.global.shared::cta.bulk_group [%0], [%1], %2;"
                     :: "l"(gaddr), "r"(saddr), "r"(bytes) : "memory");
        asm volatile("cp.async.bulk.commit_group;" ::: "memory");
        asm volatile("cp.async.bulk.wait_group 0;" ::: "memory");
    }
}

extern "C" void kernel_launch(void* const* d_in, const int* in_sizes, int n_in,
                              void* d_out, int out_size)
{
    const float* R          = (const float*)d_in[0];
    const float* pair_mask  = (const float*)d_in[1];
    const float* point_mask = (const float*)d_in[2];
    const int*   idx_i      = (const int*)d_in[3];
    const int*   idx_j      = (const int*)d_in[4];

    const int n_pairs = in_sizes[1];
    const int n       = in_sizes[2];

    float* rbf_out = (float*)d_out;
    float* chi_out = rbf_out + (size_t)n_pairs * NRBF;

    cudaMemsetAsync(chi_out, 0, (size_t)n * 8 * sizeof(float), 0);

    pack_R_kernel<<<(n + 255) / 256, 256>>>(R, n);

    int blocks = (n_pairs + PAIRS_PER_BLOCK - 1) / PAIRS_PER_BLOCK;
    geo_kernel<<<blocks, 256>>>(pair_mask, point_mask, idx_i, idx_j,
                                rbf_out, chi_out, n_pairs);
}

// round 8
// speedup vs baseline: 1.7699x; 1.1086x over previous
#include <cuda_runtime.h>
#include <math.h>
#include <stdint.h>

#define NRBF 32
#define RCAP 131072
__device__ float4 g_R4[RCAP];

// step = 5/31, width = 5/32
#define STEP      (0.16129032258064516f)
#define INV_W     (6.4f)
#define S_RATIO   (1.03225806451612903f)   // step/width
#define HALF_S2   (0.53277835587929240f)   // 0.5*(step/width)^2
#define G_CONST   (0.34453600290f)         // exp(-(step/width)^2)
#define R_CUTF    (5.0f)
#define U0_MAX    (13.0f)

#define C1  (0.48860251190291992f)
#define C2A (1.09254843059207907f)
#define C2B (0.31539156525252005f)
#define C2C (0.54627421529603953f)

#define PAIRS_PER_BLOCK 128   // 256 threads, 2 per pair

// FMA/ALU-only expf (no MUFU). Valid for x in [-85, +14].
__device__ __forceinline__ float fast_exp(float x) {
    float t  = x * 1.44269504f;
    float fi = rintf(t);
    int   ei = (int)fi;
    float g  = fmaf(fi, -0.693147182f, x);
    float p  = 1.9875691500e-4f;
    p = fmaf(p, g, 1.3981999507e-3f);
    p = fmaf(p, g, 8.3334519073e-3f);
    p = fmaf(p, g, 4.1665795894e-2f);
    p = fmaf(p, g, 1.6666665459e-1f);
    p = fmaf(p, g, 5.0000001201e-1f);
    float e = fmaf(g * g, p, g) + 1.0f;
    return __int_as_float(__float_as_int(e) + (ei << 23));
}

__global__ void __launch_bounds__(256)
pack_R_kernel(const float* __restrict__ R, int n)
{
    int i = blockIdx.x * 256 + threadIdx.x;
    if (i < n) {
        g_R4[i] = make_float4(R[3*(size_t)i], R[3*(size_t)i + 1],
                              R[3*(size_t)i + 2], 0.f);
    }
}

// 2 threads per pair. rbf: register ladder -> rotated conflict-free STS ->
// one cp.async.bulk per block (issued BEFORE chi work; waited at the end).
__global__ void __launch_bounds__(256, 6)
geo_kernel(const float* __restrict__ pair_mask,
           const float* __restrict__ point_mask,
           const int*   __restrict__ idx_i,
           const int*   __restrict__ idx_j,
           float* __restrict__ rbf_out,
           float* __restrict__ chi_out,
           int n_pairs)
{
    __shared__ __align__(16) float tile[PAIRS_PER_BLOCK * NRBF];

    const int tid  = threadIdx.x;
    const int lane = tid & 31;
    const int s    = tid >> 1;          // pair index within block (0..127)
    const int h    = tid & 1;           // half-row / channel group
    const long long p = (long long)blockIdx.x * PAIRS_PER_BLOCK + s;
    const bool valid  = (p < (long long)n_pairs);

    int i = 0, j = 0;
    float pm = 0.f;
    if (valid) {
        i  = __ldg(idx_i + p);
        j  = __ldg(idx_j + p);
        pm = __ldg(pair_mask + p);
    }

    float rx = 0.f, ry = 0.f, rz = 0.f;
    if (valid) {
        const float4 a = g_R4[j];
        const float4 b = g_R4[i];
        rx = (a.x - b.x) * pm;
        ry = (a.y - b.y) * pm;
        rz = (a.z - b.z) * pm;
    }

    const float sq  = fmaf(rx, rx, fmaf(ry, ry, rz * rz));
    const float inv = (sq > 0.f) ? rsqrtf(sq) : 0.f;
    const float d   = sq * inv * pm;

    // ---- rbf half-row: anchor at k = 16h+8, two-sided ladder ----
    const float cm   = (float)(16 * h + 8) * STEP;
    const float u0   = (d - cm) * INV_W;
    const float u0r  = fminf(fmaxf(u0, -U0_MAX), U0_MAX);
    const float kill = (fabsf(u0) < U0_MAX) ? pm : 0.f;
    const float A  = fast_exp(-0.5f * u0r * u0r) * kill;
    const float qu = fast_exp(fmaf(u0r, S_RATIO, -HALF_S2));
    float rq = __uint_as_float(0x7EF311C3u - __float_as_uint(qu));
    rq = rq * (2.0f - qu * rq);
    rq = rq * (2.0f - qu * rq);
    rq = rq * (2.0f - qu * rq);
    const float qd = G_CONST * rq;

    float x[16];
    x[8] = A;
    {
        float r = A, q = qd;
        #pragma unroll
        for (int m = 7; m >= 0; --m) { r *= q; q *= G_CONST; x[m] = r; }
    }
    {
        float r = A, q = qu;
        #pragma unroll
        for (int m = 9; m < 16; ++m) { r *= q; q *= G_CONST; x[m] = r; }
    }

    // ---- rotated STS: slot t stores quad (t+s)&3 (8-lane phases conflict-free) ----
    {
        const float4 Q0 = make_float4(x[0],  x[1],  x[2],  x[3]);
        const float4 Q1 = make_float4(x[4],  x[5],  x[6],  x[7]);
        const float4 Q2 = make_float4(x[8],  x[9],  x[10], x[11]);
        const float4 Q3 = make_float4(x[12], x[13], x[14], x[15]);
        char* rowp = (char*)tile + s * 128 + h * 64;
        #pragma unroll
        for (int t = 0; t < 4; ++t) {
            int q = (t + s) & 3;
            float4 a0 = (q & 1) ? Q1 : Q0;
            float4 a1 = (q & 1) ? Q3 : Q2;
            float4 r  = (q & 2) ? a1 : a0;
            *(float4*)(rowp + q * 16) = r;
        }
    }

    // ---- kick off the bulk copy NOW; chi work below overlaps the DMA ----
    __syncthreads();
    if (tid == 0) {
        asm volatile("fence.proxy.async.shared::cta;" ::: "memory");
        long long p0   = (long long)blockIdx.x * PAIRS_PER_BLOCK;
        long long rows = (long long)n_pairs - p0;
        int nrows = (rows >= PAIRS_PER_BLOCK) ? PAIRS_PER_BLOCK : (int)rows;
        unsigned bytes = (unsigned)nrows * (NRBF * 4);
        uint32_t saddr;
        asm("{ .reg .u64 t; cvta.to.shared.u64 t, %1; cvt.u32.u64 %0, t; }"
            : "=r"(saddr) : "l"(tile));
        unsigned long long gaddr =
            (unsigned long long)(rbf_out + (size_t)p0 * NRBF);
        asm volatile("cp.async.bulk.global.shared::cta.bulk_group [%0], [%1], %2;"
                     :: "l"(gaddr), "r"(saddr), "r"(bytes) : "memory");
        asm volatile("cp.async.bulk.commit_group;" ::: "memory");
    }

    // ---- phi (cutoff): cos(pi*x) = -sin(pi*(x-1/2)) odd polynomial ----
    const float xx = d * 0.2f;
    const float hh = xx - 0.5f;
    const float v  = hh * hh;
    float sp = fmaf(v, fmaf(v, fmaf(v, fmaf(v, 0.0821458866f, -0.599264529f),
                                    2.55016404f), -5.16771278f), 3.14159265f);
    const float cospix = -hh * sp;
    const float phi = (d < R_CUTF) ? 0.5f * (cospix + 1.0f) * pm : 0.f;

    // ---- spherical harmonics: channels [4h, 4h+4) ----
    const float um = (d != 0.f) ? inv : 0.f;
    const float ux = rx * um * pm;
    const float uy = ry * um * pm;
    const float uz = rz * um * pm;

    const float pmi   = valid ? __ldg(point_mask + i) : 0.f;
    const float scale = phi * pm * pmi;

    const float lo0 = C1 * uy;
    const float lo1 = C1 * uz;
    const float lo2 = C1 * ux;
    const float lo3 = C2A * ux * uy;
    const float hi0 = C2A * uy * uz;
    const float hi1 = C2B * fmaf(3.f, uz * uz, -1.f);
    const float hi2 = C2A * ux * uz;
    const float hi3 = C2C * (ux * ux - uy * uy);

    float val0 = (h ? hi0 : lo0) * scale;
    float val1 = (h ? hi1 : lo1) * scale;
    float val2 = (h ? hi2 : lo2) * scale;
    float val3 = (h ? hi3 : lo3) * scale;

    // ---- segmented reduction over the 16 pair-slots (even offsets keep h) ----
    int ii = valid ? i : -1;
    const unsigned full = 0xffffffffu;
    #pragma unroll
    for (int off = 2; off < 32; off <<= 1) {
        int   i2 = __shfl_down_sync(full, ii, off);
        bool take = (lane + off < 32) && (i2 == ii);
        float f0 = __shfl_down_sync(full, val0, off);
        float f1 = __shfl_down_sync(full, val1, off);
        float f2 = __shfl_down_sync(full, val2, off);
        float f3 = __shfl_down_sync(full, val3, off);
        if (take) { val0 += f0; val1 += f1; val2 += f2; val3 += f3; }
    }
    int iprev = __shfl_up_sync(full, ii, 2);
    bool leader = (lane < 2) || (iprev != ii);
    if (leader && valid) {
        float* dst = chi_out + (size_t)ii * 8 + 4 * h;
        atomicAdd(dst + 0, val0);
        atomicAdd(dst + 1, val1);
        atomicAdd(dst + 2, val2);
        atomicAdd(dst + 3, val3);
    }

    // ---- only now drain the DMA (smem stays live until warp 0 exits) ----
    if (tid == 0) {
        asm volatile("cp.async.bulk.wait_group 0;" ::: "memory");
    }
}

extern "C" void kernel_launch(void* const* d_in, const int* in_sizes, int n_in,
                              void* d_out, int out_size)
{
    const float* R          = (const float*)d_in[0];
    const float* pair_mask  = (const float*)d_in[1];
    const float* point_mask = (const float*)d_in[2];
    const int*   idx_i      = (const int*)d_in[3];
    const int*   idx_j      = (const int*)d_in[4];

    const int n_pairs = in_sizes[1];
    const int n       = in_sizes[2];

    float* rbf_out = (float*)d_out;
    float* chi_out = rbf_out + (size_t)n_pairs * NRBF;

    cudaMemsetAsync(chi_out, 0, (size_t)n * 8 * sizeof(float), 0);

    pack_R_kernel<<<(n + 255) / 256, 256>>>(R, n);

    int blocks = (n_pairs + PAIRS_PER_BLOCK - 1) / PAIRS_PER_BLOCK;
    geo_kernel<<<blocks, 256>>>(pair_mask, point_mask, idx_i, idx_j,
                                rbf_out, chi_out, n_pairs);
}

// round 9
// speedup vs baseline: 1.9283x; 1.0895x over previous
#include <cuda_runtime.h>
#include <math.h>
#include <stdint.h>

#define NRBF 32
#define RCAP 131072
__device__ float4 g_R4[RCAP];

// step = 5/31, width = 5/32
#define STEP      (0.16129032258064516f)
#define INV_W     (6.4f)
#define S_RATIO   (1.03225806451612903f)   // step/width
#define HALF_S2   (0.53277835587929240f)   // 0.5*(step/width)^2
#define G_CONST   (0.34453600290f)         // exp(-(step/width)^2)
#define R_CUTF    (5.0f)
#define U0_MAX    (13.0f)

#define C1  (0.48860251190291992f)
#define C2A (1.09254843059207907f)
#define C2B (0.31539156525252005f)
#define C2C (0.54627421529603953f)

#define PAIRS_PER_BLOCK 128   // 256 threads, 2 per pair

// FMA/ALU-only expf (no MUFU). Valid for x in [-85, +14].
__device__ __forceinline__ float fast_exp(float x) {
    float t  = x * 1.44269504f;
    float fi = rintf(t);
    int   ei = (int)fi;
    float g  = fmaf(fi, -0.693147182f, x);
    float p  = 1.9875691500e-4f;
    p = fmaf(p, g, 1.3981999507e-3f);
    p = fmaf(p, g, 8.3334519073e-3f);
    p = fmaf(p, g, 4.1665795894e-2f);
    p = fmaf(p, g, 1.6666665459e-1f);
    p = fmaf(p, g, 5.0000001201e-1f);
    float e = fmaf(g * g, p, g) + 1.0f;
    return __int_as_float(__float_as_int(e) + (ei << 23));
}

// Fused init: pack R into float4 table AND zero the chi region (one launch).
__global__ void __launch_bounds__(256)
init_kernel(const float* __restrict__ R, float4* __restrict__ chi4, int n)
{
    int i = blockIdx.x * 256 + threadIdx.x;
    if (i < n) {
        g_R4[i] = make_float4(R[3*(size_t)i], R[3*(size_t)i + 1],
                              R[3*(size_t)i + 2], 0.f);
        const float4 z = make_float4(0.f, 0.f, 0.f, 0.f);
        chi4[2*(size_t)i]     = z;    // chi row = 8 floats = 2 float4
        chi4[2*(size_t)i + 1] = z;
    }
}

// 2 threads per pair. FULL=true when n_pairs % PAIRS_PER_BLOCK == 0 (no guards).
template <bool FULL>
__global__ void __launch_bounds__(256, 6)
geo_kernel(const float* __restrict__ pair_mask,
           const float* __restrict__ point_mask,
           const int*   __restrict__ idx_i,
           const int*   __restrict__ idx_j,
           float* __restrict__ rbf_out,
           float* __restrict__ chi_out,
           int n_pairs)
{
    __shared__ __align__(16) float tile[PAIRS_PER_BLOCK * NRBF];

    const int tid  = threadIdx.x;
    const int lane = tid & 31;
    const int s    = tid >> 1;          // pair index within block (0..127)
    const int h    = tid & 1;           // half-row / channel group
    const long long p = (long long)blockIdx.x * PAIRS_PER_BLOCK + s;
    const bool valid  = FULL || (p < (long long)n_pairs);

    int i = 0, j = 0;
    float pm = 0.f;
    if (valid) {
        i  = __ldg(idx_i + p);
        j  = __ldg(idx_j + p);
        pm = __ldg(pair_mask + p);
    }

    float rx = 0.f, ry = 0.f, rz = 0.f;
    if (valid) {
        const float4 a = g_R4[j];
        const float4 b = g_R4[i];
        rx = (a.x - b.x) * pm;
        ry = (a.y - b.y) * pm;
        rz = (a.z - b.z) * pm;
    }

    const float sq  = fmaf(rx, rx, fmaf(ry, ry, rz * rz));
    const float inv = (sq > 0.f) ? rsqrtf(sq) : 0.f;
    const float d   = sq * inv * pm;

    // ---- rbf half-row: anchor at k = 16h+8, two-sided ladder ----
    const float cm   = (float)(16 * h + 8) * STEP;
    const float u0   = (d - cm) * INV_W;
    const float u0r  = fminf(fmaxf(u0, -U0_MAX), U0_MAX);
    const float kill = (fabsf(u0) < U0_MAX) ? pm : 0.f;
    const float A  = fast_exp(-0.5f * u0r * u0r) * kill;
    const float qu = fast_exp(fmaf(u0r, S_RATIO, -HALF_S2));
    float rq = __uint_as_float(0x7EF311C3u - __float_as_uint(qu));
    rq = rq * (2.0f - qu * rq);
    rq = rq * (2.0f - qu * rq);
    rq = rq * (2.0f - qu * rq);
    const float qd = G_CONST * rq;

    float x[16];
    x[8] = A;
    {
        float r = A, q = qd;
        #pragma unroll
        for (int m = 7; m >= 0; --m) { r *= q; q *= G_CONST; x[m] = r; }
    }
    {
        float r = A, q = qu;
        #pragma unroll
        for (int m = 9; m < 16; ++m) { r *= q; q *= G_CONST; x[m] = r; }
    }

    // ---- rotated STS: slot t stores quad (t+s)&3 (conflict-free phases) ----
    {
        const float4 Q0 = make_float4(x[0],  x[1],  x[2],  x[3]);
        const float4 Q1 = make_float4(x[4],  x[5],  x[6],  x[7]);
        const float4 Q2 = make_float4(x[8],  x[9],  x[10], x[11]);
        const float4 Q3 = make_float4(x[12], x[13], x[14], x[15]);
        char* rowp = (char*)tile + s * 128 + h * 64;
        #pragma unroll
        for (int t = 0; t < 4; ++t) {
            int q = (t + s) & 3;
            float4 a0 = (q & 1) ? Q1 : Q0;
            float4 a1 = (q & 1) ? Q3 : Q2;
            float4 r  = (q & 2) ? a1 : a0;
            *(float4*)(rowp + q * 16) = r;
        }
    }

    // ---- kick off the bulk copy NOW; chi work below overlaps the DMA ----
    __syncthreads();
    if (tid == 0) {
        asm volatile("fence.proxy.async.shared::cta;" ::: "memory");
        long long p0 = (long long)blockIdx.x * PAIRS_PER_BLOCK;
        unsigned bytes;
        if (FULL) {
            bytes = PAIRS_PER_BLOCK * NRBF * 4;
        } else {
            long long rows = (long long)n_pairs - p0;
            int nrows = (rows >= PAIRS_PER_BLOCK) ? PAIRS_PER_BLOCK : (int)rows;
            bytes = (unsigned)nrows * (NRBF * 4);
        }
        uint32_t saddr;
        asm("{ .reg .u64 t; cvta.to.shared.u64 t, %1; cvt.u32.u64 %0, t; }"
            : "=r"(saddr) : "l"(tile));
        unsigned long long gaddr =
            (unsigned long long)(rbf_out + (size_t)p0 * NRBF);
        asm volatile("cp.async.bulk.global.shared::cta.bulk_group [%0], [%1], %2;"
                     :: "l"(gaddr), "r"(saddr), "r"(bytes) : "memory");
        asm volatile("cp.async.bulk.commit_group;" ::: "memory");
    }

    // ---- phi (cutoff): cos(pi*x) = -sin(pi*(x-1/2)) odd polynomial ----
    const float xx = d * 0.2f;
    const float hh = xx - 0.5f;
    const float v  = hh * hh;
    float sp = fmaf(v, fmaf(v, fmaf(v, fmaf(v, 0.0821458866f, -0.599264529f),
                                    2.55016404f), -5.16771278f), 3.14159265f);
    const float cospix = -hh * sp;
    const float phi = (d < R_CUTF) ? 0.5f * (cospix + 1.0f) * pm : 0.f;

    // ---- spherical harmonics: channels [4h, 4h+4) ----
    const float um = (d != 0.f) ? inv : 0.f;
    const float ux = rx * um * pm;
    const float uy = ry * um * pm;
    const float uz = rz * um * pm;

    const float pmi   = valid ? __ldg(point_mask + i) : 0.f;
    const float scale = phi * pm * pmi;

    const float lo0 = C1 * uy;
    const float lo1 = C1 * uz;
    const float lo2 = C1 * ux;
    const float lo3 = C2A * ux * uy;
    const float hi0 = C2A * uy * uz;
    const float hi1 = C2B * fmaf(3.f, uz * uz, -1.f);
    const float hi2 = C2A * ux * uz;
    const float hi3 = C2C * (ux * ux - uy * uy);

    float val0 = (h ? hi0 : lo0) * scale;
    float val1 = (h ? hi1 : lo1) * scale;
    float val2 = (h ? hi2 : lo2) * scale;
    float val3 = (h ? hi3 : lo3) * scale;

    // ---- segmented reduction over the 16 pair-slots (even offsets keep h) ----
    int ii = valid ? i : -1;
    const unsigned full = 0xffffffffu;
    #pragma unroll
    for (int off = 2; off < 32; off <<= 1) {
        int   i2 = __shfl_down_sync(full, ii, off);
        bool take = (lane + off < 32) && (i2 == ii);
        float f0 = __shfl_down_sync(full, val0, off);
        float f1 = __shfl_down_sync(full, val1, off);
        float f2 = __shfl_down_sync(full, val2, off);
        float f3 = __shfl_down_sync(full, val3, off);
        if (take) { val0 += f0; val1 += f1; val2 += f2; val3 += f3; }
    }
    int iprev = __shfl_up_sync(full, ii, 2);
    bool leader = (lane < 2) || (iprev != ii);
    if (leader && valid) {
        // one vector red.global per leader (sm_90+), 16B-aligned by construction
        float4* dst = (float4*)(chi_out + (size_t)ii * 8 + 4 * h);
        atomicAdd(dst, make_float4(val0, val1, val2, val3));
    }

    // ---- drain the DMA last (smem stays live until warp 0 exits) ----
    if (tid == 0) {
        asm volatile("cp.async.bulk.wait_group 0;" ::: "memory");
    }
}

extern "C" void kernel_launch(void* const* d_in, const int* in_sizes, int n_in,
                              void* d_out, int out_size)
{
    const float* R          = (const float*)d_in[0];
    const float* pair_mask  = (const float*)d_in[1];
    const float* point_mask = (const float*)d_in[2];
    const int*   idx_i      = (const int*)d_in[3];
    const int*   idx_j      = (const int*)d_in[4];

    const int n_pairs = in_sizes[1];
    const int n       = in_sizes[2];

    float* rbf_out = (float*)d_out;
    float* chi_out = rbf_out + (size_t)n_pairs * NRBF;

    init_kernel<<<(n + 255) / 256, 256>>>(R, (float4*)chi_out, n);

    int blocks = (n_pairs + PAIRS_PER_BLOCK - 1) / PAIRS_PER_BLOCK;
    if ((n_pairs % PAIRS_PER_BLOCK) == 0) {
        geo_kernel<true><<<blocks, 256>>>(pair_mask, point_mask, idx_i, idx_j,
                                          rbf_out, chi_out, n_pairs);
    } else {
        geo_kernel<false><<<blocks, 256>>>(pair_mask, point_mask, idx_i, idx_j,
                                           rbf_out, chi_out, n_pairs);
    }
}

// round 10
// speedup vs baseline: 1.9462x; 1.0093x over previous
#include <cuda_runtime.h>
#include <math.h>
#include <stdint.h>

#define NRBF 32
#define RCAP 131072
__device__ float4 g_R4[RCAP];

// step = 5/31, width = 5/32
#define STEP      (0.16129032258064516f)
#define INV_W     (6.4f)
#define S_RATIO   (1.03225806451612903f)   // step/width
#define HALF_S2   (0.53277835587929240f)   // 0.5*(step/width)^2
#define G_CONST   (0.34453600290f)         // exp(-(step/width)^2)
#define R_CUTF    (5.0f)
#define U0_MAX    (13.0f)

#define C1  (0.48860251190291992f)
#define C2A (1.09254843059207907f)
#define C2B (0.31539156525252005f)
#define C2C (0.54627421529603953f)

#define PAIRS_PER_BLOCK 128   // 256 threads, 2 per pair

// FMA/ALU-only expf (no MUFU). Valid for x in [-85, +14].
__device__ __forceinline__ float fast_exp(float x) {
    float t  = x * 1.44269504f;
    float fi = rintf(t);
    int   ei = (int)fi;
    float g  = fmaf(fi, -0.693147182f, x);
    float p  = 1.9875691500e-4f;
    p = fmaf(p, g, 1.3981999507e-3f);
    p = fmaf(p, g, 8.3334519073e-3f);
    p = fmaf(p, g, 4.1665795894e-2f);
    p = fmaf(p, g, 1.6666665459e-1f);
    p = fmaf(p, g, 5.0000001201e-1f);
    float e = fmaf(g * g, p, g) + 1.0f;
    return __int_as_float(__float_as_int(e) + (ei << 23));
}

// Fused vectorized init: pack R (float4 table) + zero chi. 4 points / thread.
__global__ void __launch_bounds__(256)
init_kernel(const float4* __restrict__ R4in, float4* __restrict__ chi4, int n)
{
    unsigned t  = blockIdx.x * 256u + threadIdx.x;
    unsigned i0 = t * 4u;
    if (i0 + 3 < (unsigned)n) {
        // 4 points = 12 floats = 3 coalesced float4 loads
        float4 a = __ldg(R4in + t * 3u);
        float4 b = __ldg(R4in + t * 3u + 1);
        float4 c = __ldg(R4in + t * 3u + 2);
        g_R4[i0    ] = make_float4(a.x, a.y, a.z, 0.f);
        g_R4[i0 + 1] = make_float4(a.w, b.x, b.y, 0.f);
        g_R4[i0 + 2] = make_float4(b.z, b.w, c.x, 0.f);
        g_R4[i0 + 3] = make_float4(c.y, c.z, c.w, 0.f);
        const float4 z = make_float4(0.f, 0.f, 0.f, 0.f);
        #pragma unroll
        for (int k = 0; k < 8; ++k) chi4[(size_t)i0 * 2 + k] = z;
    } else {
        const float* Rf = (const float*)R4in;
        for (unsigned i = i0; i < (unsigned)n; ++i) {
            g_R4[i] = make_float4(Rf[3u*i], Rf[3u*i + 1], Rf[3u*i + 2], 0.f);
            const float4 z = make_float4(0.f, 0.f, 0.f, 0.f);
            chi4[(size_t)i * 2]     = z;
            chi4[(size_t)i * 2 + 1] = z;
        }
    }
}

// 2 threads per pair. FULL=true when n_pairs % PAIRS_PER_BLOCK == 0.
// All per-thread indexing is 32-bit (n_pairs*32 < 2^31).
template <bool FULL>
__global__ void __launch_bounds__(256, 6)
geo_kernel(const float* __restrict__ pair_mask,
           const float* __restrict__ point_mask,
           const int*   __restrict__ idx_i,
           const int*   __restrict__ idx_j,
           float* __restrict__ rbf_out,
           float* __restrict__ chi_out,
           int n_pairs)
{
    __shared__ __align__(16) float tile[PAIRS_PER_BLOCK * NRBF];

    const unsigned tid  = threadIdx.x;
    const unsigned lane = tid & 31u;
    const unsigned s    = tid >> 1;          // pair index within block
    const unsigned h    = tid & 1u;          // half-row / channel group
    const unsigned p    = blockIdx.x * (unsigned)PAIRS_PER_BLOCK + s;
    const bool valid    = FULL || (p < (unsigned)n_pairs);

    int i = 0, j = 0;
    float pm = 0.f;
    if (valid) {
        i  = __ldg(idx_i + p);
        j  = __ldg(idx_j + p);
        pm = __ldg(pair_mask + p);
    }

    float rx = 0.f, ry = 0.f, rz = 0.f;
    float pmi = 0.f;
    if (valid) {
        const float4 a = __ldg(&g_R4[j]);
        const float4 b = __ldg(&g_R4[i]);
        pmi = __ldg(point_mask + i);
        rx = (a.x - b.x) * pm;
        ry = (a.y - b.y) * pm;
        rz = (a.z - b.z) * pm;
    }

    const float sq  = fmaf(rx, rx, fmaf(ry, ry, rz * rz));
    const float inv = (sq > 0.f) ? rsqrtf(sq) : 0.f;
    const float d   = sq * inv * pm;

    // ---- rbf half-row: anchor at k = 16h+8, two-sided ladder ----
    const float cm   = (float)(16u * h + 8u) * STEP;
    const float u0   = (d - cm) * INV_W;
    const float u0r  = fminf(fmaxf(u0, -U0_MAX), U0_MAX);
    const float kill = (fabsf(u0) < U0_MAX) ? pm : 0.f;
    const float A  = fast_exp(-0.5f * u0r * u0r) * kill;
    const float qu = fast_exp(fmaf(u0r, S_RATIO, -HALF_S2));
    float rq = __uint_as_float(0x7EF311C3u - __float_as_uint(qu));
    rq = rq * (2.0f - qu * rq);
    rq = rq * (2.0f - qu * rq);
    rq = rq * (2.0f - qu * rq);
    const float qd = G_CONST * rq;

    float x[16];
    x[8] = A;
    {
        float r = A, q = qd;
        #pragma unroll
        for (int m = 7; m >= 0; --m) { r *= q; q *= G_CONST; x[m] = r; }
    }
    {
        float r = A, q = qu;
        #pragma unroll
        for (int m = 9; m < 16; ++m) { r *= q; q *= G_CONST; x[m] = r; }
    }

    // ---- rotated STS: slot t stores quad (t+s)&3 (conflict-free phases) ----
    {
        const float4 Q0 = make_float4(x[0],  x[1],  x[2],  x[3]);
        const float4 Q1 = make_float4(x[4],  x[5],  x[6],  x[7]);
        const float4 Q2 = make_float4(x[8],  x[9],  x[10], x[11]);
        const float4 Q3 = make_float4(x[12], x[13], x[14], x[15]);
        char* rowp = (char*)tile + (s * 128u + h * 64u);
        #pragma unroll
        for (unsigned t = 0; t < 4; ++t) {
            unsigned q = (t + s) & 3u;
            float4 a0 = (q & 1u) ? Q1 : Q0;
            float4 a1 = (q & 1u) ? Q3 : Q2;
            float4 r  = (q & 2u) ? a1 : a0;
            *(float4*)(rowp + q * 16u) = r;
        }
    }

    // ---- kick off the bulk copy NOW; chi work below overlaps the DMA ----
    __syncthreads();
    if (tid == 0) {
        asm volatile("fence.proxy.async.shared::cta;" ::: "memory");
        size_t p0 = (size_t)blockIdx.x * PAIRS_PER_BLOCK;
        unsigned bytes;
        if (FULL) {
            bytes = PAIRS_PER_BLOCK * NRBF * 4;
        } else {
            long long rows = (long long)n_pairs - (long long)p0;
            int nrows = (rows >= PAIRS_PER_BLOCK) ? PAIRS_PER_BLOCK : (int)rows;
            bytes = (unsigned)nrows * (NRBF * 4);
        }
        uint32_t saddr;
        asm("{ .reg .u64 t; cvta.to.shared.u64 t, %1; cvt.u32.u64 %0, t; }"
            : "=r"(saddr) : "l"(tile));
        unsigned long long gaddr = (unsigned long long)(rbf_out + p0 * NRBF);
        asm volatile("cp.async.bulk.global.shared::cta.bulk_group [%0], [%1], %2;"
                     :: "l"(gaddr), "r"(saddr), "r"(bytes) : "memory");
        asm volatile("cp.async.bulk.commit_group;" ::: "memory");
    }

    // ---- phi (cutoff): cos(pi*x) = -sin(pi*(x-1/2)) odd polynomial ----
    const float xx = d * 0.2f;
    const float hh = xx - 0.5f;
    const float v  = hh * hh;
    float sp = fmaf(v, fmaf(v, fmaf(v, fmaf(v, 0.0821458866f, -0.599264529f),
                                    2.55016404f), -5.16771278f), 3.14159265f);
    const float cospix = -hh * sp;
    const float phi = (d < R_CUTF) ? 0.5f * (cospix + 1.0f) * pm : 0.f;

    // ---- spherical harmonics: channels [4h, 4h+4) ----
    const float um = (d != 0.f) ? inv : 0.f;
    const float ux = rx * um * pm;
    const float uy = ry * um * pm;
    const float uz = rz * um * pm;

    const float scale = phi * pm * pmi;

    const float lo0 = C1 * uy;
    const float lo1 = C1 * uz;
    const float lo2 = C1 * ux;
    const float lo3 = C2A * ux * uy;
    const float hi0 = C2A * uy * uz;
    const float hi1 = C2B * fmaf(3.f, uz * uz, -1.f);
    const float hi2 = C2A * ux * uz;
    const float hi3 = C2C * (ux * ux - uy * uy);

    float val0 = (h ? hi0 : lo0) * scale;
    float val1 = (h ? hi1 : lo1) * scale;
    float val2 = (h ? hi2 : lo2) * scale;
    float val3 = (h ? hi3 : lo3) * scale;

    // ---- segmented reduction within 16-lane halves (8 pairs), 3 rounds ----
    int ii = valid ? i : -1;
    const unsigned full = 0xffffffffu;
    const unsigned l16  = lane & 15u;
    #pragma unroll
    for (int off = 2; off <= 8; off <<= 1) {
        int   i2 = __shfl_down_sync(full, ii, off, 16);
        bool take = (l16 + off < 16) && (i2 == ii);
        float f0 = __shfl_down_sync(full, val0, off, 16);
        float f1 = __shfl_down_sync(full, val1, off, 16);
        float f2 = __shfl_down_sync(full, val2, off, 16);
        float f3 = __shfl_down_sync(full, val3, off, 16);
        if (take) { val0 += f0; val1 += f1; val2 += f2; val3 += f3; }
    }
    int iprev = __shfl_up_sync(full, ii, 2, 16);
    bool leader = (l16 < 2) || (iprev != ii);
    if (leader && valid) {
        float4* dst = (float4*)(chi_out + (unsigned)ii * 8u + 4u * h);
        atomicAdd(dst, make_float4(val0, val1, val2, val3));
    }

    // ---- drain the DMA last (smem stays live until warp 0 exits) ----
    if (tid == 0) {
        asm volatile("cp.async.bulk.wait_group 0;" ::: "memory");
    }
}

extern "C" void kernel_launch(void* const* d_in, const int* in_sizes, int n_in,
                              void* d_out, int out_size)
{
    const float* R          = (const float*)d_in[0];
    const float* pair_mask  = (const float*)d_in[1];
    const float* point_mask = (const float*)d_in[2];
    const int*   idx_i      = (const int*)d_in[3];
    const int*   idx_j      = (const int*)d_in[4];

    const int n_pairs = in_sizes[1];
    const int n       = in_sizes[2];

    float* rbf_out = (float*)d_out;
    float* chi_out = rbf_out + (size_t)n_pairs * NRBF;

    int ithreads = (n + 3) / 4;
    init_kernel<<<(ithreads + 255) / 256, 256>>>((const float4*)R,
                                                 (float4*)chi_out, n);

    int blocks = (n_pairs + PAIRS_PER_BLOCK - 1) / PAIRS_PER_BLOCK;
    if ((n_pairs % PAIRS_PER_BLOCK) == 0) {
        geo_kernel<true><<<blocks, 256>>>(pair_mask, point_mask, idx_i, idx_j,
                                          rbf_out, chi_out, n_pairs);
    } else {
        geo_kernel<false><<<blocks, 256>>>(pair_mask, point_mask, idx_i, idx_j,
                                           rbf_out, chi_out, n_pairs);
    }
}